// round 16
// baseline (speedup 1.0000x reference)
#include <cuda_runtime.h>
#include <cuda_bf16.h>
#include <cstdint>

#define N_POINTS 131072
#define N_QUADS  (N_POINTS / 4)
#define N_NODES  2048
#define N_NPAIR  (N_NODES / 2)
#define N_GROUPS (N_NPAIR / 4)     // 256 groups of 4 node-pairs (8 nodes)
#define K_SEL    32
#define CAP      256               // max points buffered per node
#define KNN_BLOCKS  148            // 1 block/SM, balanced quad ranges
#define KNN_THREADS 224            // >= ceil(N_QUADS/148) = 222

typedef unsigned long long u64;

// Scratch (no allocations allowed). Zero-initialized at load; select resets g_cnt.
__device__ int g_cnt[N_NODES];
__device__ int g_bucket[N_NODES * CAP];

// ---- packed f32x2 helpers (per-lane RN, bit-identical to scalar __f*_rn) ----
__device__ __forceinline__ u64 pk2(float lo, float hi) {
    u64 r; asm("mov.b64 %0, {%1, %2};" : "=l"(r) : "f"(lo), "f"(hi)); return r;
}
__device__ __forceinline__ void upk2(float& lo, float& hi, u64 v) {
    asm("mov.b64 {%0, %1}, %2;" : "=f"(lo), "=f"(hi) : "l"(v));
}
__device__ __forceinline__ u64 mul2(u64 a, u64 b) {
    u64 d; asm("mul.rn.f32x2 %0, %1, %2;" : "=l"(d) : "l"(a), "l"(b)); return d;
}
__device__ __forceinline__ u64 fma2(u64 a, u64 b, u64 c) {
    u64 d; asm("fma.rn.f32x2 %0, %1, %2, %3;" : "=l"(d) : "l"(a), "l"(b), "l"(c)); return d;
}
__device__ __forceinline__ u64 add2(u64 a, u64 b) {
    u64 d; asm("add.rn.f32x2 %0, %1, %2;" : "=l"(d) : "l"(a), "l"(b)); return d;
}

// Exact reference rounding chain (scalar), used for the recompute pass:
//   r1=RN(x*nx); r2=RN(y*ny+r1); r3=RN(z*nz+r2); r4=RN(-2*r3+pp); d2=RN(r4+nn)
__device__ __forceinline__ float d2_scalar(float x, float y, float z, float pp,
                                           float nx, float ny, float nz, float nn) {
    float r = __fmul_rn(x, nx);
    r = __fmaf_rn(y, ny, r);
    r = __fmaf_rn(z, nz, r);
    r = __fmaf_rn(-2.0f, r, pp);
    return __fadd_rn(r, nn);
}

// Chain: mul2,fma2,fma2,add2,add2 with pre-scaled point (exact, == ref chain).
#define CHAIN(X, Y, Z, PP, A, C) \
    add2(add2(fma2((Z), (C).x, fma2((Y), (A).y, mul2((X), (A).x))), (PP)), (C).y)

// ---------------------------------------------------------------------------
// Kernel 1: 1-NN assign. FOUR points per thread (halves smem bytes/point vs
// 2 pts/thread -- the measured binding resource), 2 nodes per packed f32x2
// lane, tournament argmin over groups of 4 node-pairs (8 nodes).
// Exact -2 pre-scaling keeps the chain bit-identical to the reference.
// Group winner -> exact recompute; first index among equal hits ==
// jnp.argmin ascending tie-break.
// ---------------------------------------------------------------------------
extern __shared__ u64 s_nodes[];   // N_NPAIR * 4 u64 = 32 KB

__global__ void __launch_bounds__(KNN_THREADS, 1) knn_kernel(
    const float* __restrict__ pts,
    const float* __restrict__ nodes,
    float* __restrict__ out_d2,
    float* __restrict__ out_id)
{
    const int tid = threadIdx.x;

    // Fill node-pair cache (exact nn rounding as reference sum order).
    for (int m = tid; m < N_NPAIR; m += KNN_THREADS) {
        const float2* nf = (const float2*)nodes;
        float2 f0 = nf[3 * m + 0];   // nxA nyA
        float2 f1 = nf[3 * m + 1];   // nzA nxB
        float2 f2 = nf[3 * m + 2];   // nyB nzB
        float nxA = f0.x, nyA = f0.y, nzA = f1.x;
        float nxB = f1.y, nyB = f2.x, nzB = f2.y;
        float nnA = __fadd_rn(__fadd_rn(__fmul_rn(nxA, nxA), __fmul_rn(nyA, nyA)),
                              __fmul_rn(nzA, nzA));
        float nnB = __fadd_rn(__fadd_rn(__fmul_rn(nxB, nxB), __fmul_rn(nyB, nyB)),
                              __fmul_rn(nzB, nzB));
        s_nodes[4 * m + 0] = pk2(nxA, nxB);
        s_nodes[4 * m + 1] = pk2(nyA, nyB);
        s_nodes[4 * m + 2] = pk2(nzA, nzB);
        s_nodes[4 * m + 3] = pk2(nnA, nnB);
    }
    __syncthreads();

    // Balanced quad ranges: ~221-222 quads per block, one quad per thread.
    const int b     = blockIdx.x;
    const int start = (int)(((long long)b       * N_QUADS) / KNN_BLOCKS);
    const int end   = (int)(((long long)(b + 1) * N_QUADS) / KNN_BLOCKS);
    const int q     = start + tid;
    if (q >= end) return;

    // Four consecutive points (coalesced float2 loads: 6 x 8B).
    const float2* pf = (const float2*)pts;
    float2 f0 = pf[6 * q + 0];   // x0 y0
    float2 f1 = pf[6 * q + 1];   // z0 x1
    float2 f2 = pf[6 * q + 2];   // y1 z1
    float2 f3 = pf[6 * q + 3];   // x2 y2
    float2 f4 = pf[6 * q + 4];   // z2 x3
    float2 f5 = pf[6 * q + 5];   // y3 z3
    const float x0 = f0.x, y0 = f0.y, z0 = f1.x;
    const float x1 = f1.y, y1 = f2.x, z1 = f2.y;
    const float x2 = f3.x, y2 = f3.y, z2 = f4.x;
    const float x3 = f4.y, y3 = f5.x, z3 = f5.y;

    const float pp0 = __fadd_rn(__fadd_rn(__fmul_rn(x0, x0), __fmul_rn(y0, y0)), __fmul_rn(z0, z0));
    const float pp1 = __fadd_rn(__fadd_rn(__fmul_rn(x1, x1), __fmul_rn(y1, y1)), __fmul_rn(z1, z1));
    const float pp2 = __fadd_rn(__fadd_rn(__fmul_rn(x2, x2), __fmul_rn(y2, y2)), __fmul_rn(z2, z2));
    const float pp3 = __fadd_rn(__fadd_rn(__fmul_rn(x3, x3), __fmul_rn(y3, y3)), __fmul_rn(z3, z3));

    // Exact -2 pre-scaled coordinates (exponent shift, no rounding).
    const u64 X0 = pk2(-2.0f*x0, -2.0f*x0), Y0 = pk2(-2.0f*y0, -2.0f*y0), Z0 = pk2(-2.0f*z0, -2.0f*z0), PP0 = pk2(pp0, pp0);
    const u64 X1 = pk2(-2.0f*x1, -2.0f*x1), Y1 = pk2(-2.0f*y1, -2.0f*y1), Z1 = pk2(-2.0f*z1, -2.0f*z1), PP1 = pk2(pp1, pp1);
    const u64 X2 = pk2(-2.0f*x2, -2.0f*x2), Y2 = pk2(-2.0f*y2, -2.0f*y2), Z2 = pk2(-2.0f*z2, -2.0f*z2), PP2 = pk2(pp2, pp2);
    const u64 X3 = pk2(-2.0f*x3, -2.0f*x3), Y3 = pk2(-2.0f*y3, -2.0f*y3), Z3 = pk2(-2.0f*z3, -2.0f*z3), PP3 = pk2(pp3, pp3);

    float best0 = __int_as_float(0x7f800000), best1 = best0, best2 = best0, best3 = best0;
    int   grp0 = 0, grp1 = 0, grp2 = 0, grp3 = 0;

    const ulonglong2* sv = (const ulonglong2*)s_nodes;   // 2 x 16B per node-pair

#pragma unroll 1
    for (int g = 0; g < N_GROUPS; g++) {
        // Load 4 node-pairs (8 nodes) for this group: 8 x LDS.128 serve 4 points.
        ulonglong2 a0 = sv[8 * g + 0], c0 = sv[8 * g + 1];
        ulonglong2 a1 = sv[8 * g + 2], c1 = sv[8 * g + 3];
        ulonglong2 a2 = sv[8 * g + 4], c2 = sv[8 * g + 5];
        ulonglong2 a3 = sv[8 * g + 6], c3 = sv[8 * g + 7];

        // Point 0
        u64 q0 = CHAIN(X0, Y0, Z0, PP0, a0, c0);
        u64 q1 = CHAIN(X0, Y0, Z0, PP0, a1, c1);
        u64 q2 = CHAIN(X0, Y0, Z0, PP0, a2, c2);
        u64 q3 = CHAIN(X0, Y0, Z0, PP0, a3, c3);
        {
            float u0,v0,u1,v1,u2,v2,u3,v3;
            upk2(u0,v0,q0); upk2(u1,v1,q1); upk2(u2,v2,q2); upk2(u3,v3,q3);
            float t = fminf(fminf(fminf(u0,v0), fminf(u1,v1)),
                            fminf(fminf(u2,v2), fminf(u3,v3)));
            if (t < best0) { best0 = t; grp0 = g; }
        }
        // Point 1
        q0 = CHAIN(X1, Y1, Z1, PP1, a0, c0);
        q1 = CHAIN(X1, Y1, Z1, PP1, a1, c1);
        q2 = CHAIN(X1, Y1, Z1, PP1, a2, c2);
        q3 = CHAIN(X1, Y1, Z1, PP1, a3, c3);
        {
            float u0,v0,u1,v1,u2,v2,u3,v3;
            upk2(u0,v0,q0); upk2(u1,v1,q1); upk2(u2,v2,q2); upk2(u3,v3,q3);
            float t = fminf(fminf(fminf(u0,v0), fminf(u1,v1)),
                            fminf(fminf(u2,v2), fminf(u3,v3)));
            if (t < best1) { best1 = t; grp1 = g; }
        }
        // Point 2
        q0 = CHAIN(X2, Y2, Z2, PP2, a0, c0);
        q1 = CHAIN(X2, Y2, Z2, PP2, a1, c1);
        q2 = CHAIN(X2, Y2, Z2, PP2, a2, c2);
        q3 = CHAIN(X2, Y2, Z2, PP2, a3, c3);
        {
            float u0,v0,u1,v1,u2,v2,u3,v3;
            upk2(u0,v0,q0); upk2(u1,v1,q1); upk2(u2,v2,q2); upk2(u3,v3,q3);
            float t = fminf(fminf(fminf(u0,v0), fminf(u1,v1)),
                            fminf(fminf(u2,v2), fminf(u3,v3)));
            if (t < best2) { best2 = t; grp2 = g; }
        }
        // Point 3
        q0 = CHAIN(X3, Y3, Z3, PP3, a0, c0);
        q1 = CHAIN(X3, Y3, Z3, PP3, a1, c1);
        q2 = CHAIN(X3, Y3, Z3, PP3, a2, c2);
        q3 = CHAIN(X3, Y3, Z3, PP3, a3, c3);
        {
            float u0,v0,u1,v1,u2,v2,u3,v3;
            upk2(u0,v0,q0); upk2(u1,v1,q1); upk2(u2,v2,q2); upk2(u3,v3,q3);
            float t = fminf(fminf(fminf(u0,v0), fminf(u1,v1)),
                            fminf(fminf(u2,v2), fminf(u3,v3)));
            if (t < best3) { best3 = t; grp3 = g; }
        }
    }

    // Recompute winning groups bit-exactly (reference chain); first index among
    // equal hits (ascending j) == reference argmin tie-break.
    const float px[4] = {x0, x1, x2, x3};
    const float py[4] = {y0, y1, y2, y3};
    const float pz[4] = {z0, z1, z2, z3};
    const float ppp[4] = {pp0, pp1, pp2, pp3};
    const float bst[4] = {best0, best1, best2, best3};
    const int   grp[4] = {grp0, grp1, grp2, grp3};

#pragma unroll
    for (int k = 0; k < 4; k++) {
        int idx = 0x7FFFFFFF;
#pragma unroll
        for (int t = 0; t < 4; t++) {
            int m = 4 * grp[k] + t;
            ulonglong2 a = sv[2 * m + 0], c = sv[2 * m + 1];
            float nxA, nxB, nyA, nyB, nzA, nzB, nnA, nnB;
            upk2(nxA, nxB, a.x); upk2(nyA, nyB, a.y);
            upk2(nzA, nzB, c.x); upk2(nnA, nnB, c.y);
            float dA = d2_scalar(px[k], py[k], pz[k], ppp[k], nxA, nyA, nzA, nnA);
            float dB = d2_scalar(px[k], py[k], pz[k], ppp[k], nxB, nyB, nzB, nnB);
            if (dA == bst[k]) idx = min(idx, 2 * m);
            if (dB == bst[k]) idx = min(idx, 2 * m + 1);
        }
        const int pt = 4 * q + k;
        out_d2[pt] = bst[k];
        out_id[pt] = (float)idx;
        int pos = atomicAdd(&g_cnt[idx], 1);
        if (pos < CAP) g_bucket[idx * CAP + pos] = pt;
    }
}

// ---------------------------------------------------------------------------
// Kernel 2: per-node selection, one warp per node (proven 6.2-7.2us).
// ---------------------------------------------------------------------------
#define CE(a, b) { unsigned lo = min(a, b), hi = max(a, b); a = lo; b = hi; }

__global__ void __launch_bounds__(256) select_kernel(float* __restrict__ out_patch) {
    const int lane = threadIdx.x & 31;
    const int node = blockIdx.x * 8 + (threadIdx.x >> 5);
    const unsigned INF = 0x7FFFFFFFu;

    const int cnt = g_cnt[node];
    const int cl  = cnt < CAP ? cnt : CAP;
    if (lane == 0) g_cnt[node] = 0;      // reset for next graph replay

    const int base = node * CAP;
    unsigned e0 = (lane       < cl) ? (unsigned)g_bucket[base + lane      ] : INF;
    unsigned e1 = (lane + 32  < cl) ? (unsigned)g_bucket[base + lane + 32 ] : INF;
    unsigned e2 = (lane + 64  < cl) ? (unsigned)g_bucket[base + lane + 64 ] : INF;
    unsigned e3 = (lane + 96  < cl) ? (unsigned)g_bucket[base + lane + 96 ] : INF;
    unsigned e4 = (lane + 128 < cl) ? (unsigned)g_bucket[base + lane + 128] : INF;
    unsigned e5 = (lane + 160 < cl) ? (unsigned)g_bucket[base + lane + 160] : INF;
    unsigned e6 = (lane + 192 < cl) ? (unsigned)g_bucket[base + lane + 192] : INF;
    unsigned e7 = (lane + 224 < cl) ? (unsigned)g_bucket[base + lane + 224] : INF;

    // Batcher odd-even merge sort network for 8 (19 compare-exchanges).
    CE(e0, e1) CE(e2, e3) CE(e4, e5) CE(e6, e7)
    CE(e0, e2) CE(e1, e3) CE(e4, e6) CE(e5, e7)
    CE(e1, e2) CE(e5, e6)
    CE(e0, e4) CE(e1, e5) CE(e2, e6) CE(e3, e7)
    CE(e2, e4) CE(e3, e5)
    CE(e1, e2) CE(e3, e4) CE(e5, e6)

    unsigned keep = INF;
#pragma unroll
    for (int t = 0; t < K_SEL; t++) {
        unsigned m = __reduce_min_sync(0xFFFFFFFFu, e0);
        if (lane == t) keep = m;
        bool hit = (e0 == m);            // unique indices: at most one real hit
        e0 = hit ? e1 : e0;
        e1 = hit ? e2 : e1;
        e2 = hit ? e3 : e2;
        e3 = hit ? e4 : e3;
        e4 = hit ? e5 : e4;
        e5 = hit ? e6 : e5;
        e6 = hit ? e7 : e6;
        e7 = hit ? INF : e7;
    }

    out_patch[node * K_SEL + lane] = (lane < cl) ? (float)keep : 0.0f;
}

// ---------------------------------------------------------------------------
// Launch: outputs concatenated as [min_d2 | pcd_id | patch], all float32.
// ---------------------------------------------------------------------------
extern "C" void kernel_launch(void* const* d_in, const int* in_sizes, int n_in,
                              void* d_out, int out_size)
{
    const float* pts   = (const float*)d_in[0];   // [131072, 3]
    const float* nodes = (const float*)d_in[1];   // [2048, 3]

    float* out       = (float*)d_out;
    float* out_d2    = out;                        // 131072
    float* out_id    = out + N_POINTS;             // 131072
    float* out_patch = out + 2 * N_POINTS;         // 2048*32

    const size_t smem_bytes = (size_t)N_NPAIR * 4 * sizeof(u64);  // 32 KB
    (void)cudaFuncSetAttribute(knn_kernel,
                               cudaFuncAttributeMaxDynamicSharedMemorySize,
                               (int)smem_bytes);

    knn_kernel<<<KNN_BLOCKS, KNN_THREADS, smem_bytes>>>(pts, nodes, out_d2, out_id);
    select_kernel<<<N_NODES / 8, 256>>>(out_patch);
}